// round 14
// baseline (speedup 1.0000x reference)
#include <cuda_runtime.h>
#include <math.h>

#define C_    256
#define H_    50
#define W_    50
#define R_    128
#define PH_   7
#define PW_   7
#define NBIN  49
#define BH_   10
#define BW_   10
#define SS_   0.0625f
#define SI_   1.0f
#define SO_   1.8f
#define SLOTS 40

// f32 RN reciprocal of 7 (XLA divide-by-constant fold) — bit-exact vs reference.
#define RCP7 (1.0f / 7.0f)

__device__ float g_ft[H_ * W_ * C_];   // transposed features [(h*W+w)*C + c]

struct Geo {
    int hs, he, ws, we;
    int hs_in, he_in, ws_in, we_in;
    float bsh, bsw;
};

__device__ __forceinline__ int rnd_f(float v) {
    return (int)floorf(__fadd_rn(__fmul_rn(v, SS_), 0.5f));
}

__device__ __forceinline__ Geo compute_geo(const float* __restrict__ rois, int r) {
    const float x1 = rois[r * 5 + 1];
    const float y1 = rois[r * 5 + 2];
    const float x2 = rois[r * 5 + 3];
    const float y2 = rois[r * 5 + 4];
    const float cx = __fmul_rn(__fadd_rn(x1, x2), 0.5f);
    const float cy = __fmul_rn(__fadd_rn(y1, y2), 0.5f);
    const float wh = __fmul_rn(__fsub_rn(x2, x1), 0.5f);
    const float hh = __fmul_rn(__fsub_rn(y2, y1), 0.5f);

    Geo g;
    g.hs    = rnd_f(__fsub_rn(cy, __fmul_rn(hh, SO_)));
    g.he    = rnd_f(__fadd_rn(cy, __fmul_rn(hh, SO_)));
    g.ws    = rnd_f(__fsub_rn(cx, __fmul_rn(wh, SO_)));
    g.we    = rnd_f(__fadd_rn(cx, __fmul_rn(wh, SO_)));
    g.hs_in = rnd_f(__fsub_rn(cy, __fmul_rn(hh, SI_)));
    g.he_in = rnd_f(__fadd_rn(cy, __fmul_rn(hh, SI_)));
    g.ws_in = rnd_f(__fsub_rn(cx, __fmul_rn(wh, SI_)));
    g.we_in = rnd_f(__fadd_rn(cx, __fmul_rn(wh, SI_)));

    const float roi_h = (float)max(g.he - g.hs + 1, 1);
    const float roi_w = (float)max(g.we - g.ws + 1, 1);
    g.bsh = __fmul_rn(roi_h, RCP7);
    g.bsw = __fmul_rn(roi_w, RCP7);
    return g;
}

// ---------------------------------------------------------------------------
// Kernel 1: transpose (C, H*W) -> (H*W, C), vectorized.
// ---------------------------------------------------------------------------
__global__ __launch_bounds__(256) void transpose_kernel(const float* __restrict__ f) {
    __shared__ float tile[32][33];
    const int P = H_ * W_;                 // 2500
    const int p0 = blockIdx.x * 32;
    const int c0 = blockIdx.y * 32;
    const int tid = threadIdx.x;

    {
        const int c_l = tid >> 3;
        const int p4  = (tid & 7) * 4;
        const int p   = p0 + p4;
        const float* src = f + (c0 + c_l) * P + p;
        if (p + 3 < P) {
            const float4 v = __ldg((const float4*)src);
            tile[c_l][p4 + 0] = v.x;
            tile[c_l][p4 + 1] = v.y;
            tile[c_l][p4 + 2] = v.z;
            tile[c_l][p4 + 3] = v.w;
        } else {
            #pragma unroll
            for (int k = 0; k < 4; ++k)
                tile[c_l][p4 + k] = (p + k < P) ? __ldg(src + k) : 0.0f;
        }
    }
    __syncthreads();
    {
        const int p_l = tid >> 3;
        const int c4  = (tid & 7) * 4;
        const int p   = p0 + p_l;
        if (p < P) {
            float4 v;
            v.x = tile[c4 + 0][p_l];
            v.y = tile[c4 + 1][p_l];
            v.z = tile[c4 + 2][p_l];
            v.w = tile[c4 + 3][p_l];
            *(float4*)(g_ft + p * C_ + c0 + c4) = v;
        }
    }
}

// ---------------------------------------------------------------------------
// Kernel 2: pooling. grid = R * 7(ph) * 2(channel half) = 1792 blocks,
// block = 224 (7 warps, warp = pw). Lane owns 4 channels (one float4 lane).
// __launch_bounds__(224, 8) caps regs at 36 -> 8 blocks/SM (87% occupancy).
// ---------------------------------------------------------------------------
__global__ __launch_bounds__(224, 8) void pool_kernel(const float* __restrict__ rois,
                                                      float* __restrict__ out) {
    const int bx   = blockIdx.x;
    const int r    = bx / 14;
    const int rem  = bx % 14;
    const int ph   = rem >> 1;
    const int half = rem & 1;
    const int tid  = threadIdx.x;
    const int lane = tid & 31;
    const int warp = tid >> 5;            // = pw

    __shared__ int   pos_s[PW_ * SLOTS];
    __shared__ float tile[PW_ * 132];     // [pw][c_local], pad 132

    const Geo g = compute_geo(rois, r);

    // ---- per-warp bin bounds (bit-exact) ----
    int hstart = (int)floorf(__fmul_rn((float)ph,         g.bsh)) + g.hs;
    int hend   = (int)ceilf (__fmul_rn((float)(ph + 1),   g.bsh)) + g.hs;
    int wstart = (int)floorf(__fmul_rn((float)warp,       g.bsw)) + g.ws;
    int wend   = (int)ceilf (__fmul_rn((float)(warp + 1), g.bsw)) + g.ws;
    hstart = min(max(hstart, 0), H_);
    hend   = min(max(hend,   0), H_);
    wstart = min(max(wstart, 0), W_);
    wend   = min(max(wend,   0), W_);

    const int hspan = max(min(hend, hstart + BH_) - hstart, 0);
    const int wspan = max(min(wend, wstart + BW_) - wstart, 0);
    const int cells = hspan * wspan;

    // ---- ballot-compacted position list ----
    int* dst = pos_s + warp * SLOTS;
    int cnt = 0;
    for (int base = 0; base < cells; base += 32) {
        const int cell = base + lane;
        bool valid = false;
        int  off = 0;
        if (cell < cells) {
            const int h = hstart + cell / wspan;
            const int w = wstart + cell % wspan;
            const bool ih = (h > g.hs_in) && (h < g.he_in);
            const bool iw = (w > g.ws_in) && (w < g.we_in);
            valid = !(ih && iw);
            off = (h * W_ + w) * C_;
        }
        const unsigned mask = __ballot_sync(0xffffffffu, valid);
        if (valid)
            dst[cnt + __popc(mask & ((1u << lane) - 1u))] = off;
        cnt += __popc(mask);
    }

    // ---- gather + max: lane covers channels [half*128 + 4*lane .. +3] ----
    const float* f0 = g_ft + half * 128 + lane * 4;

    float4 m0 = make_float4(-INFINITY, -INFINITY, -INFINITY, -INFINITY);
    float4 m1 = m0;
    int i = 0;
    for (; i + 2 <= cnt; i += 2) {
        const float4 v0 = __ldg((const float4*)(f0 + dst[i + 0]));
        const float4 v1 = __ldg((const float4*)(f0 + dst[i + 1]));
        m0.x = fmaxf(m0.x, v0.x); m0.y = fmaxf(m0.y, v0.y);
        m0.z = fmaxf(m0.z, v0.z); m0.w = fmaxf(m0.w, v0.w);
        m1.x = fmaxf(m1.x, v1.x); m1.y = fmaxf(m1.y, v1.y);
        m1.z = fmaxf(m1.z, v1.z); m1.w = fmaxf(m1.w, v1.w);
    }
    if (i < cnt) {
        const float4 v0 = __ldg((const float4*)(f0 + dst[i]));
        m0.x = fmaxf(m0.x, v0.x); m0.y = fmaxf(m0.y, v0.y);
        m0.z = fmaxf(m0.z, v0.z); m0.w = fmaxf(m0.w, v0.w);
    }
    m0.x = fmaxf(m0.x, m1.x); m0.y = fmaxf(m0.y, m1.y);
    m0.z = fmaxf(m0.z, m1.z); m0.w = fmaxf(m0.w, m1.w);
    if (cnt == 0) m0 = make_float4(0.f, 0.f, 0.f, 0.f);

    // ---- stage to smem [pw][c_local] ----
    *(float4*)(tile + warp * 132 + lane * 4) = m0;
    __syncthreads();

    // ---- store: out[r][half*128 + c][ph*7 + pw] ----
    float* outp = out + ((size_t)r * C_ + half * 128) * NBIN + ph * PW_;
    for (int j = tid; j < 128 * PW_; j += 224) {
        const int c = j / PW_;
        const int m = j % PW_;
        outp[c * NBIN + m] = tile[m * 132 + c];
    }
}

// ---------------------------------------------------------------------------
extern "C" void kernel_launch(void* const* d_in, const int* in_sizes, int n_in,
                              void* d_out, int out_size) {
    const float* features = (const float*)d_in[0];
    const float* rois     = (const float*)d_in[1];
    if (n_in >= 2 && in_sizes[0] == R_ * 5 && in_sizes[1] == C_ * H_ * W_) {
        const float* t = features; features = rois; rois = t;
    }
    float* out = (float*)d_out;

    dim3 tg((H_ * W_ + 31) / 32, C_ / 32);   // (79, 8)
    transpose_kernel<<<tg, 256>>>(features);
    pool_kernel<<<R_ * 14, 224>>>(rois, out);
}

// round 15
// speedup vs baseline: 1.4138x; 1.4138x over previous
#include <cuda_runtime.h>
#include <math.h>

#define C_    256
#define H_    50
#define W_    50
#define R_    128
#define PH_   7
#define PW_   7
#define NBIN  49
#define BH_   10
#define BW_   10
#define SS_   0.0625f
#define SI_   1.0f
#define SO_   1.8f
#define SLOTS 40

// f32 RN reciprocal of 7 (XLA divide-by-constant fold) — bit-exact vs reference.
#define RCP7 (1.0f / 7.0f)

__device__ float g_ft[H_ * W_ * C_];   // transposed features [(h*W+w)*C + c]

__device__ __forceinline__ int rnd_f(float v) {
    return (int)floorf(__fadd_rn(__fmul_rn(v, SS_), 0.5f));
}

// ---------------------------------------------------------------------------
// Kernel 1: transpose (C, H*W) -> (H*W, C), vectorized (proven).
// ---------------------------------------------------------------------------
__global__ __launch_bounds__(256) void transpose_kernel(const float* __restrict__ f) {
    __shared__ float tile[32][33];
    const int P = H_ * W_;                 // 2500
    const int p0 = blockIdx.x * 32;
    const int c0 = blockIdx.y * 32;
    const int tid = threadIdx.x;

    {
        const int c_l = tid >> 3;
        const int p4  = (tid & 7) * 4;
        const int p   = p0 + p4;
        const float* src = f + (c0 + c_l) * P + p;
        if (p + 3 < P) {
            const float4 v = __ldg((const float4*)src);
            tile[c_l][p4 + 0] = v.x;
            tile[c_l][p4 + 1] = v.y;
            tile[c_l][p4 + 2] = v.z;
            tile[c_l][p4 + 3] = v.w;
        } else {
            #pragma unroll
            for (int k = 0; k < 4; ++k)
                tile[c_l][p4 + k] = (p + k < P) ? __ldg(src + k) : 0.0f;
        }
    }
    __syncthreads();
    {
        const int p_l = tid >> 3;
        const int c4  = (tid & 7) * 4;
        const int p   = p0 + p_l;
        if (p < P) {
            float4 v;
            v.x = tile[c4 + 0][p_l];
            v.y = tile[c4 + 1][p_l];
            v.z = tile[c4 + 2][p_l];
            v.w = tile[c4 + 3][p_l];
            *(float4*)(g_ft + p * C_ + c0 + c4) = v;
        }
    }
}

// ---------------------------------------------------------------------------
// Kernel 2: pooling (round-13 structure + occupancy fix).
// grid = R*7 (roi, ph), block = 224 (warp = pw). Lane owns 8 channels
// (two float4 streams). __launch_bounds__(224, 7) caps regs at 41 ->
// 7 blocks/SM (~76% occupancy) vs 5 (45%) at regs=50.
// ---------------------------------------------------------------------------
__global__ __launch_bounds__(224, 7) void pool_kernel(const float* __restrict__ rois,
                                                      float* __restrict__ out) {
    const int r    = blockIdx.x / 7;
    const int ph   = blockIdx.x % 7;
    const int tid  = threadIdx.x;
    const int lane = tid & 31;
    const int warp = tid >> 5;            // = pw

    __shared__ int   pos_s[PW_ * SLOTS];
    __shared__ float tile[PW_ * 260];     // [pw][c], pad 260

    // ---- per-ROI geometry (bit-exact vs reference) ----
    const float x1 = rois[r * 5 + 1];
    const float y1 = rois[r * 5 + 2];
    const float x2 = rois[r * 5 + 3];
    const float y2 = rois[r * 5 + 4];
    const float cx = __fmul_rn(__fadd_rn(x1, x2), 0.5f);
    const float cy = __fmul_rn(__fadd_rn(y1, y2), 0.5f);
    const float wh = __fmul_rn(__fsub_rn(x2, x1), 0.5f);
    const float hh = __fmul_rn(__fsub_rn(y2, y1), 0.5f);

    const int hs    = rnd_f(__fsub_rn(cy, __fmul_rn(hh, SO_)));
    const int he    = rnd_f(__fadd_rn(cy, __fmul_rn(hh, SO_)));
    const int ws    = rnd_f(__fsub_rn(cx, __fmul_rn(wh, SO_)));
    const int we    = rnd_f(__fadd_rn(cx, __fmul_rn(wh, SO_)));
    const int hs_in = rnd_f(__fsub_rn(cy, __fmul_rn(hh, SI_)));
    const int he_in = rnd_f(__fadd_rn(cy, __fmul_rn(hh, SI_)));
    const int ws_in = rnd_f(__fsub_rn(cx, __fmul_rn(wh, SI_)));
    const int we_in = rnd_f(__fadd_rn(cx, __fmul_rn(wh, SI_)));

    const float bsh = __fmul_rn((float)max(he - hs + 1, 1), RCP7);
    const float bsw = __fmul_rn((float)max(we - ws + 1, 1), RCP7);

    int hstart = (int)floorf(__fmul_rn((float)ph,         bsh)) + hs;
    int hend   = (int)ceilf (__fmul_rn((float)(ph + 1),   bsh)) + hs;
    int wstart = (int)floorf(__fmul_rn((float)warp,       bsw)) + ws;
    int wend   = (int)ceilf (__fmul_rn((float)(warp + 1), bsw)) + ws;
    hstart = min(max(hstart, 0), H_);
    hend   = min(max(hend,   0), H_);
    wstart = min(max(wstart, 0), W_);
    wend   = min(max(wend,   0), W_);

    const int hspan = max(min(hend, hstart + BH_) - hstart, 0);
    const int wspan = max(min(wend, wstart + BW_) - wstart, 0);
    const int cells = hspan * wspan;

    // ---- ballot-compacted position list (order-free under max) ----
    int* dst = pos_s + warp * SLOTS;
    int cnt = 0;
    for (int base = 0; base < cells; base += 32) {
        const int cell = base + lane;
        bool valid = false;
        int  off = 0;
        if (cell < cells) {
            const int h = hstart + cell / wspan;
            const int w = wstart + cell % wspan;
            const bool ih = (h > hs_in) && (h < he_in);
            const bool iw = (w > ws_in) && (w < we_in);
            valid = !(ih && iw);
            off = (h * W_ + w) * C_;
        }
        const unsigned mask = __ballot_sync(0xffffffffu, valid);
        if (valid)
            dst[cnt + __popc(mask & ((1u << lane) - 1u))] = off;
        cnt += __popc(mask);
    }

    // ---- gather + max: lane covers channels 4*lane and 4*lane+128 ----
    const int cl = lane * 4;
    const float* f0 = g_ft + cl;
    const float* f1 = g_ft + cl + 128;

    float4 a = make_float4(-INFINITY, -INFINITY, -INFINITY, -INFINITY);
    float4 b = a;
    for (int i = 0; i < cnt; ++i) {
        const int p = dst[i];
        const float4 v0 = __ldg((const float4*)(f0 + p));
        const float4 v1 = __ldg((const float4*)(f1 + p));
        a.x = fmaxf(a.x, v0.x); a.y = fmaxf(a.y, v0.y);
        a.z = fmaxf(a.z, v0.z); a.w = fmaxf(a.w, v0.w);
        b.x = fmaxf(b.x, v1.x); b.y = fmaxf(b.y, v1.y);
        b.z = fmaxf(b.z, v1.z); b.w = fmaxf(b.w, v1.w);
    }
    if (cnt == 0) {
        a = make_float4(0.f, 0.f, 0.f, 0.f);
        b = a;
    }

    // ---- stage to smem [pw][c] ----
    float* trow = tile + warp * 260;
    *(float4*)(trow + cl)       = a;
    *(float4*)(trow + cl + 128) = b;
    __syncthreads();

    // ---- store: out[r][c][ph*7 + pw] ----
    float* outp = out + (size_t)r * C_ * NBIN + ph * PW_;
    for (int j = tid; j < C_ * PW_; j += 224) {
        const int c = j / PW_;
        const int m = j % PW_;
        outp[c * NBIN + m] = tile[m * 260 + c];
    }
}

// ---------------------------------------------------------------------------
extern "C" void kernel_launch(void* const* d_in, const int* in_sizes, int n_in,
                              void* d_out, int out_size) {
    const float* features = (const float*)d_in[0];
    const float* rois     = (const float*)d_in[1];
    if (n_in >= 2 && in_sizes[0] == R_ * 5 && in_sizes[1] == C_ * H_ * W_) {
        const float* t = features; features = rois; rois = t;
    }
    float* out = (float*)d_out;

    dim3 tg((H_ * W_ + 31) / 32, C_ / 32);   // (79, 8)
    transpose_kernel<<<tg, 256>>>(features);
    pool_kernel<<<R_ * 7, 224>>>(rois, out);
}